// round 11
// baseline (speedup 1.0000x reference)
#include <cuda_runtime.h>
#include <cstdint>

// Problem constants
#define BATCH      256
#define OUTN       64
#define IN_F       262144      // 4*256*256
// Tiling
#define BM         64          // batch rows per block
#define KB         256         // split-K blocks
#define QPKB       256         // quads per K-block
#define QPS        16          // quads per stage
#define NSTAGES    16
#define NTHREADS   128
#define WSTRIDE    36          // 32 k + 4 pad: conflict-free B frags

// Deterministic split-K scratch
__device__ float g_partial[KB * BATCH * OUTN];   // 16 MB
__device__ float g_p2[8 * BATCH * OUTN];         // 512 KB

__device__ __forceinline__ unsigned f2tf(float f) {
    unsigned u; asm("cvt.rna.tf32.f32 %0, %1;" : "=r"(u) : "f"(f)); return u;
}

__global__ __launch_bounds__(NTHREADS, 5)
void wl_gemm(const float* __restrict__ x, const float* __restrict__ W)
{
    // ts: tf32-converted A tile, paired (t4,t4+4) + XOR-swizzled, stride 64. 16 KB.
    __shared__ __align__(16) unsigned ts[BM * 64];
    // ws: two half-K (32-col) W buffers. 2 x 9 KB.
    __shared__ __align__(16) float ws[2][OUTN * WSTRIDE];

    const int tid  = threadIdx.x;
    const int lane = tid & 31;
    const int warp = tid >> 5;
    const int mt   = blockIdx.x;       // 0..3
    const int kb   = blockIdx.y;       // 0..255
    const int rowbase = mt * BM;

    const int g  = lane >> 2;          // mma groupID
    const int t4 = lane & 3;           // mma thread-in-group
    const int mrow0 = (warp & 1) * 32;
    const int ncol0 = (warp >> 1) * 32;

    const int cpos  = tid & 7;         // x loader: float4 position
    const int brow0 = tid >> 3;        // x loader: row group

    float acc[2][4][4];
#pragma unroll
    for (int m = 0; m < 2; ++m)
#pragma unroll
        for (int n = 0; n < 4; ++n)
#pragma unroll
            for (int j = 0; j < 4; ++j) acc[m][n][j] = 0.0f;

    float4 tp[4], bt[4];               // x prefetch registers (one stage)

#define PREFETCH_X(ch, r2, c0)                                                  \
    _Pragma("unroll")                                                           \
    for (int it = 0; it < 4; ++it) {                                            \
        const int br = brow0 + it * 16;                                         \
        const float* xr = x + (size_t)(rowbase + br) * IN_F                     \
                            + (ch) * 65536 + (2 * (r2)) * 256 + 2 * (c0) + cpos * 4; \
        tp[it] = __ldcs((const float4*)xr);                                     \
        bt[it] = __ldcs((const float4*)(xr + 256));                             \
    }

// Load one half-stage of W: bands {2*hb, 2*hb+1} -> ws[hb], 512 x 16B chunks.
#define CP_W_HALF(ch, r2, c0, hb)                                               \
    {                                                                           \
        float* wbuf = &ws[hb][0];                                               \
        _Pragma("unroll")                                                       \
        for (int it = 0; it < 4; ++it) {                                        \
            const int u  = it * 128 + tid;                                      \
            const int o  = u >> 3;            /* 0..63 */                       \
            const int f4 = u & 7;                                               \
            const int bl = f4 >> 2;           /* band_local 0/1 */              \
            const int c4 = (f4 & 3) * 4;                                        \
            const float* src = W + (size_t)o * IN_F                             \
                + (size_t)((ch) * 4 + (hb) * 2 + bl) * 16384                    \
                + (size_t)(r2) * 128 + (c0) + c4;                               \
            const unsigned dst = (unsigned)__cvta_generic_to_shared(            \
                &wbuf[o * WSTRIDE + bl * 16 + c4]);                             \
            asm volatile("cp.async.cg.shared.global [%0], [%1], 16;\n"          \
                         :: "r"(dst), "l"(src));                                \
        }                                                                       \
        asm volatile("cp.async.commit_group;\n");                               \
    }

// mma over one half (ks = 4*hb .. 4*hb+3)
#define MMA_HALF(hb)                                                            \
    {                                                                           \
        const float* wbuf = &ws[hb][0];                                         \
        _Pragma("unroll")                                                       \
        for (int ksl = 0; ksl < 4; ++ksl) {                                     \
            const int ks = (hb) * 4 + ksl;                                      \
            const int c2 = ((((ks ^ g) << 2) | (t4 ^ (g & 3))) << 1);           \
            unsigned a[2][4];                                                   \
            _Pragma("unroll")                                                   \
            for (int m = 0; m < 2; ++m) {                                       \
                const int rA = mrow0 + m * 16 + g;                              \
                const uint2 pa = *(const uint2*)&ts[(rA << 6) + c2];            \
                const uint2 pb = *(const uint2*)&ts[((rA + 8) << 6) + c2];      \
                a[m][0] = pa.x; a[m][1] = pb.x; a[m][2] = pa.y; a[m][3] = pb.y; \
            }                                                                   \
            _Pragma("unroll")                                                   \
            for (int n = 0; n < 4; ++n) {                                       \
                const int nc = ncol0 + n * 8;                                   \
                const unsigned b0 = f2tf(wbuf[(nc + g) * WSTRIDE + ksl * 8 + t4]);     \
                const unsigned b1 = f2tf(wbuf[(nc + g) * WSTRIDE + ksl * 8 + 4 + t4]); \
                _Pragma("unroll")                                               \
                for (int m = 0; m < 2; ++m) {                                   \
                    asm volatile(                                               \
                        "mma.sync.aligned.m16n8k8.row.col.f32.tf32.tf32.f32 "   \
                        "{%0,%1,%2,%3}, {%4,%5,%6,%7}, {%8,%9}, {%0,%1,%2,%3};\n" \
                        : "+f"(acc[m][n][0]), "+f"(acc[m][n][1]),               \
                          "+f"(acc[m][n][2]), "+f"(acc[m][n][3])                \
                        : "r"(a[m][0]), "r"(a[m][1]), "r"(a[m][2]), "r"(a[m][3]), \
                          "r"(b0), "r"(b1));                                    \
                }                                                               \
            }                                                                   \
        }                                                                       \
    }

    // ---------------- prologue ----------------
    {
        const int qb = kb * QPKB;
        const int ch = qb >> 14, r2 = (qb >> 7) & 127, c0 = qb & 127;
        PREFETCH_X(ch, r2, c0);
        CP_W_HALF(ch, r2, c0, 0);
        CP_W_HALF(ch, r2, c0, 1);
    }

    for (int s = 0; s < NSTAGES; ++s) {
        // ---- butterfly: x regs -> tf32 -> ts (paired+swizzled). ts safe:
        //      prev iter's bottom sync covers mma(s-1) reads. ----
#pragma unroll
        for (int it = 0; it < 4; ++it) {
            const int br  = brow0 + it * 16;
            const int r3  = br & 7;
            const int rx3 = r3 & 3;

            const float apb0 = tp[it].x + tp[it].y, amb0 = tp[it].x - tp[it].y;
            const float cpd0 = bt[it].x + bt[it].y, cmd0 = bt[it].x - bt[it].y;
            const float apb1 = tp[it].z + tp[it].w, amb1 = tp[it].z - tp[it].w;
            const float cpd1 = bt[it].z + bt[it].w, cmd1 = bt[it].z - bt[it].w;

            const float v0[4] = { (apb0 + cpd0) * 0.5f, (apb0 - cpd0) * 0.5f,
                                  (amb0 + cmd0) * 0.5f, (amb0 - cmd0) * 0.5f };
            const float v1[4] = { (apb1 + cpd1) * 0.5f, (apb1 - cpd1) * 0.5f,
                                  (amb1 + cmd1) * 0.5f, (amb1 - cmd1) * 0.5f };

            // q = 0 : c2l = 2*cpos
            {
                const int c2l = 2 * cpos;
                const int sub = c2l >> 3, t4q = c2l & 3, hfq = (c2l >> 2) & 1;
#pragma unroll
                for (int band = 0; band < 4; ++band) {
                    const int ks   = 2 * band + sub;
                    const int col2 = ((ks ^ r3) << 2) | (t4q ^ rx3);
                    ts[br * 64 + col2 * 2 + hfq] = f2tf(v0[band]);
                }
            }
            // q = 1 : c2l = 2*cpos + 1
            {
                const int c2l = 2 * cpos + 1;
                const int sub = c2l >> 3, t4q = c2l & 3, hfq = (c2l >> 2) & 1;
#pragma unroll
                for (int band = 0; band < 4; ++band) {
                    const int ks   = 2 * band + sub;
                    const int col2 = ((ks ^ r3) << 2) | (t4q ^ rx3);
                    ts[br * 64 + col2 * 2 + hfq] = f2tf(v1[band]);
                }
            }
        }

        // ---- prefetch next-stage x into regs (max lead over the two mma halves) ----
        if (s + 1 < NSTAGES) {
            const int qn = kb * QPKB + (s + 1) * QPS;
            const int chn = qn >> 14, r2n = (qn >> 7) & 127, c0n = qn & 127;
            PREFETCH_X(chn, r2n, c0n);
        }

        __syncthreads();                           // ts ready for all warps

        asm volatile("cp.async.wait_group 1;\n");  // W(s, half0) arrived
        MMA_HALF(0);

        __syncthreads();                           // all warps done reading ws[0]
        if (s + 1 < NSTAGES) {
            const int qn = kb * QPKB + (s + 1) * QPS;
            const int chn = qn >> 14, r2n = (qn >> 7) & 127, c0n = qn & 127;
            CP_W_HALF(chn, r2n, c0n, 0);
            asm volatile("cp.async.wait_group 1;\n");  // W(s, half1) arrived
        } else {
            asm volatile("cp.async.wait_group 0;\n");
        }
        MMA_HALF(1);

        __syncthreads();                           // ws[1] free AND ts free
        if (s + 1 < NSTAGES) {
            const int qn = kb * QPKB + (s + 1) * QPS;
            const int chn = qn >> 14, r2n = (qn >> 7) & 127, c0n = qn & 127;
            CP_W_HALF(chn, r2n, c0n, 1);
        }
    }

    // ---- write split-K partial tile ----
    float* pp = g_partial + (size_t)kb * (BATCH * OUTN);
#pragma unroll
    for (int m = 0; m < 2; ++m)
#pragma unroll
        for (int n = 0; n < 4; ++n) {
            const int r = rowbase + mrow0 + m * 16 + g;
            const int c = ncol0 + n * 8 + 2 * t4;
            *(float2*)&pp[r * OUTN + c]       = make_float2(acc[m][n][0], acc[m][n][1]);
            *(float2*)&pp[(r + 8) * OUTN + c] = make_float2(acc[m][n][2], acc[m][n][3]);
        }
}

// Stage 1: 8 groups of 32 kb-slices each. Fully parallel, coalesced.
__global__ __launch_bounds__(256)
void wl_reduce1()
{
    const int idx = blockIdx.x * 256 + threadIdx.x;   // 0..131071
    const int e   = idx & (BATCH * OUTN - 1);
    const int grp = idx >> 14;                         // 0..7
    const float* p = g_partial + (size_t)(grp * 32) * (BATCH * OUTN) + e;
    float ssum = 0.0f;
#pragma unroll
    for (int j = 0; j < 32; ++j)
        ssum += p[(size_t)j * (BATCH * OUTN)];
    g_p2[idx] = ssum;
}

// Stage 2: fold 8 groups + bias.
__global__ __launch_bounds__(256)
void wl_reduce2(const float* __restrict__ bias, float* __restrict__ out)
{
    const int e = blockIdx.x * 256 + threadIdx.x;     // 0..16383
    float ssum = bias[e & (OUTN - 1)];
#pragma unroll
    for (int gi = 0; gi < 8; ++gi)
        ssum += g_p2[gi * (BATCH * OUTN) + e];
    out[e] = ssum;
}

extern "C" void kernel_launch(void* const* d_in, const int* in_sizes, int n_in,
                              void* d_out, int out_size)
{
    const float* x  = (const float*)d_in[0];   // [256, 262144]
    const float* W  = (const float*)d_in[1];   // [64, 262144]
    const float* bb = (const float*)d_in[2];   // [64]
    float* out = (float*)d_out;                // [256, 64]

    dim3 grid(4, KB);   // x-major: the 4 M-tiles sharing a W slice are co-resident (L2 reuse)
    wl_gemm<<<grid, NTHREADS>>>(x, W);
    wl_reduce1<<<512, 256>>>();
    wl_reduce2<<<64, 256>>>(bb, out);
}

// round 17
// speedup vs baseline: 1.4949x; 1.4949x over previous
#include <cuda_runtime.h>
#include <cstdint>

// Problem constants
#define BATCH      256
#define OUTN       64
#define IN_F       262144      // 4*256*256
// Tiling
#define BM         64          // batch rows per block
#define KB         256         // split-K blocks
#define QPKB       256         // quads per K-block
#define QPS        16          // quads per stage
#define NSTAGES    16
#define NTHREADS   128
#define WSTRIDE    36          // 32 k + 4 pad: conflict-free B frags

// Deterministic split-K scratch
__device__ float g_partial[KB * BATCH * OUTN];   // 16 MB
__device__ float g_p2[8 * BATCH * OUTN];         // 512 KB

__device__ __forceinline__ unsigned f2tf(float f) {
    unsigned u; asm("cvt.rna.tf32.f32 %0, %1;" : "=r"(u) : "f"(f)); return u;
}

__global__ __launch_bounds__(NTHREADS, 5)
void wl_gemm(const float* __restrict__ x, const float* __restrict__ W)
{
    // ts: tf32-converted A tile, paired (t4,t4+4) + XOR-swizzled, stride 64. 16 KB.
    __shared__ __align__(16) unsigned ts[BM * 64];
    // ws: two half-K (32-col) W buffers. 2 x 9 KB.
    __shared__ __align__(16) float ws[2][OUTN * WSTRIDE];

    const int tid  = threadIdx.x;
    const int lane = tid & 31;
    const int warp = tid >> 5;
    const int mt   = blockIdx.x;       // 0..3
    const int kb   = blockIdx.y;       // 0..255
    const int rowbase = mt * BM;

    const int g  = lane >> 2;          // mma groupID
    const int t4 = lane & 3;           // mma thread-in-group
    const int mrow0 = (warp & 1) * 32;
    const int ncol0 = (warp >> 1) * 32;

    const int cpos  = tid & 7;         // x loader: float4 position
    const int brow0 = tid >> 3;        // x loader: row group

    float acc[2][4][4];
#pragma unroll
    for (int m = 0; m < 2; ++m)
#pragma unroll
        for (int n = 0; n < 4; ++n)
#pragma unroll
            for (int j = 0; j < 4; ++j) acc[m][n][j] = 0.0f;

    float4 tp[4], bt[4];               // x prefetch registers (one stage)

#define PREFETCH_X(ch, r2, c0)                                                  \
    _Pragma("unroll")                                                           \
    for (int it = 0; it < 4; ++it) {                                            \
        const int br = brow0 + it * 16;                                         \
        const float* xr = x + (size_t)(rowbase + br) * IN_F                     \
                            + (ch) * 65536 + (2 * (r2)) * 256 + 2 * (c0) + cpos * 4; \
        tp[it] = __ldcs((const float4*)xr);                                     \
        bt[it] = __ldcs((const float4*)(xr + 256));                             \
    }

// Load one half-stage of W: bands {2*hb, 2*hb+1} -> ws[hb], 512 x 16B chunks.
#define CP_W_HALF(ch, r2, c0, hb)                                               \
    {                                                                           \
        float* wbuf = &ws[hb][0];                                               \
        _Pragma("unroll")                                                       \
        for (int it = 0; it < 4; ++it) {                                        \
            const int u  = it * 128 + tid;                                      \
            const int o  = u >> 3;            /* 0..63 */                       \
            const int f4 = u & 7;                                               \
            const int bl = f4 >> 2;           /* band_local 0/1 */              \
            const int c4 = (f4 & 3) * 4;                                        \
            const float* src = W + (size_t)o * IN_F                             \
                + (size_t)((ch) * 4 + (hb) * 2 + bl) * 16384                    \
                + (size_t)(r2) * 128 + (c0) + c4;                               \
            const unsigned dst = (unsigned)__cvta_generic_to_shared(            \
                &wbuf[o * WSTRIDE + bl * 16 + c4]);                             \
            asm volatile("cp.async.cg.shared.global [%0], [%1], 16;\n"          \
                         :: "r"(dst), "l"(src));                                \
        }                                                                       \
        asm volatile("cp.async.commit_group;\n");                               \
    }

// mma over one half (ks = 4*hb .. 4*hb+3)
#define MMA_HALF(hb)                                                            \
    {                                                                           \
        const float* wbuf = &ws[hb][0];                                         \
        _Pragma("unroll")                                                       \
        for (int ksl = 0; ksl < 4; ++ksl) {                                     \
            const int ks = (hb) * 4 + ksl;                                      \
            const int c2 = ((((ks ^ g) << 2) | (t4 ^ (g & 3))) << 1);           \
            unsigned a[2][4];                                                   \
            _Pragma("unroll")                                                   \
            for (int m = 0; m < 2; ++m) {                                       \
                const int rA = mrow0 + m * 16 + g;                              \
                const uint2 pa = *(const uint2*)&ts[(rA << 6) + c2];            \
                const uint2 pb = *(const uint2*)&ts[((rA + 8) << 6) + c2];      \
                a[m][0] = pa.x; a[m][1] = pb.x; a[m][2] = pa.y; a[m][3] = pb.y; \
            }                                                                   \
            _Pragma("unroll")                                                   \
            for (int n = 0; n < 4; ++n) {                                       \
                const int nc = ncol0 + n * 8;                                   \
                const unsigned b0 = f2tf(wbuf[(nc + g) * WSTRIDE + ksl * 8 + t4]);     \
                const unsigned b1 = f2tf(wbuf[(nc + g) * WSTRIDE + ksl * 8 + 4 + t4]); \
                _Pragma("unroll")                                               \
                for (int m = 0; m < 2; ++m) {                                   \
                    asm volatile(                                               \
                        "mma.sync.aligned.m16n8k8.row.col.f32.tf32.tf32.f32 "   \
                        "{%0,%1,%2,%3}, {%4,%5,%6,%7}, {%8,%9}, {%0,%1,%2,%3};\n" \
                        : "+f"(acc[m][n][0]), "+f"(acc[m][n][1]),               \
                          "+f"(acc[m][n][2]), "+f"(acc[m][n][3])                \
                        : "r"(a[m][0]), "r"(a[m][1]), "r"(a[m][2]), "r"(a[m][3]), \
                          "r"(b0), "r"(b1));                                    \
                }                                                               \
            }                                                                   \
        }                                                                       \
    }

    // ---------------- prologue ----------------
    {
        const int qb = kb * QPKB;
        const int ch = qb >> 14, r2 = (qb >> 7) & 127, c0 = qb & 127;
        PREFETCH_X(ch, r2, c0);
        CP_W_HALF(ch, r2, c0, 0);
        CP_W_HALF(ch, r2, c0, 1);
    }

    for (int s = 0; s < NSTAGES; ++s) {
        // ---- butterfly: x regs -> tf32 -> ts (paired+swizzled).
        //      ts write-safe: sync #4 of iter s-1 is after all mma reads of s-1. ----
#pragma unroll
        for (int it = 0; it < 4; ++it) {
            const int br  = brow0 + it * 16;
            const int r3  = br & 7;
            const int rx3 = r3 & 3;

            const float apb0 = tp[it].x + tp[it].y, amb0 = tp[it].x - tp[it].y;
            const float cpd0 = bt[it].x + bt[it].y, cmd0 = bt[it].x - bt[it].y;
            const float apb1 = tp[it].z + tp[it].w, amb1 = tp[it].z - tp[it].w;
            const float cpd1 = bt[it].z + bt[it].w, cmd1 = bt[it].z - bt[it].w;

            const float v0[4] = { (apb0 + cpd0) * 0.5f, (apb0 - cpd0) * 0.5f,
                                  (amb0 + cmd0) * 0.5f, (amb0 - cmd0) * 0.5f };
            const float v1[4] = { (apb1 + cpd1) * 0.5f, (apb1 - cpd1) * 0.5f,
                                  (amb1 + cmd1) * 0.5f, (amb1 - cmd1) * 0.5f };

            // q = 0 : c2l = 2*cpos
            {
                const int c2l = 2 * cpos;
                const int sub = c2l >> 3, t4q = c2l & 3, hfq = (c2l >> 2) & 1;
#pragma unroll
                for (int band = 0; band < 4; ++band) {
                    const int ks   = 2 * band + sub;
                    const int col2 = ((ks ^ r3) << 2) | (t4q ^ rx3);
                    ts[br * 64 + col2 * 2 + hfq] = f2tf(v0[band]);
                }
            }
            // q = 1 : c2l = 2*cpos + 1
            {
                const int c2l = 2 * cpos + 1;
                const int sub = c2l >> 3, t4q = c2l & 3, hfq = (c2l >> 2) & 1;
#pragma unroll
                for (int band = 0; band < 4; ++band) {
                    const int ks   = 2 * band + sub;
                    const int col2 = ((ks ^ r3) << 2) | (t4q ^ rx3);
                    ts[br * 64 + col2 * 2 + hfq] = f2tf(v1[band]);
                }
            }
        }

        // ---- prefetch next-stage x into regs (max lead over the two mma halves) ----
        if (s + 1 < NSTAGES) {
            const int qn = kb * QPKB + (s + 1) * QPS;
            const int chn = qn >> 14, r2n = (qn >> 7) & 127, c0n = qn & 127;
            PREFETCH_X(chn, r2n, c0n);
        }

        // RACE FIX: wait_group only drains *this thread's* cp.async groups.
        // Readers consume bytes copied by OTHER threads, so the order must be
        // wait_group -> __syncthreads() -> read (every thread waits, then the
        // barrier publishes all completions block-wide).
        asm volatile("cp.async.wait_group 1;\n");  // my W(s, half0) done
        __syncthreads();                           // sync #1: everyone's half0 done + ts ready
        MMA_HALF(0);

        __syncthreads();                           // sync #2: all warps done reading ws[0]
        if (s + 1 < NSTAGES) {
            const int qn = kb * QPKB + (s + 1) * QPS;
            const int chn = qn >> 14, r2n = (qn >> 7) & 127, c0n = qn & 127;
            CP_W_HALF(chn, r2n, c0n, 0);           // pending: half1(s), half0(s+1)
            asm volatile("cp.async.wait_group 1;\n");  // my W(s, half1) done
        } else {
            asm volatile("cp.async.wait_group 0;\n");
        }
        __syncthreads();                           // sync #3: everyone's half1 done
        MMA_HALF(1);

        __syncthreads();                           // sync #4: ws[1] free AND ts free
        if (s + 1 < NSTAGES) {
            const int qn = kb * QPKB + (s + 1) * QPS;
            const int chn = qn >> 14, r2n = (qn >> 7) & 127, c0n = qn & 127;
            CP_W_HALF(chn, r2n, c0n, 1);           // pending: half0(s+1), half1(s+1)
        }
    }

    // ---- write split-K partial tile ----
    float* pp = g_partial + (size_t)kb * (BATCH * OUTN);
#pragma unroll
    for (int m = 0; m < 2; ++m)
#pragma unroll
        for (int n = 0; n < 4; ++n) {
            const int r = rowbase + mrow0 + m * 16 + g;
            const int c = ncol0 + n * 8 + 2 * t4;
            *(float2*)&pp[r * OUTN + c]       = make_float2(acc[m][n][0], acc[m][n][1]);
            *(float2*)&pp[(r + 8) * OUTN + c] = make_float2(acc[m][n][2], acc[m][n][3]);
        }
}

// Stage 1: 8 groups of 32 kb-slices each. Fully parallel, coalesced.
__global__ __launch_bounds__(256)
void wl_reduce1()
{
    const int idx = blockIdx.x * 256 + threadIdx.x;   // 0..131071
    const int e   = idx & (BATCH * OUTN - 1);
    const int grp = idx >> 14;                         // 0..7
    const float* p = g_partial + (size_t)(grp * 32) * (BATCH * OUTN) + e;
    float ssum = 0.0f;
#pragma unroll
    for (int j = 0; j < 32; ++j)
        ssum += p[(size_t)j * (BATCH * OUTN)];
    g_p2[idx] = ssum;
}

// Stage 2: fold 8 groups + bias.
__global__ __launch_bounds__(256)
void wl_reduce2(const float* __restrict__ bias, float* __restrict__ out)
{
    const int e = blockIdx.x * 256 + threadIdx.x;     // 0..16383
    float ssum = bias[e & (OUTN - 1)];
#pragma unroll
    for (int gi = 0; gi < 8; ++gi)
        ssum += g_p2[gi * (BATCH * OUTN) + e];
    out[e] = ssum;
}

extern "C" void kernel_launch(void* const* d_in, const int* in_sizes, int n_in,
                              void* d_out, int out_size)
{
    const float* x  = (const float*)d_in[0];   // [256, 262144]
    const float* W  = (const float*)d_in[1];   // [64, 262144]
    const float* bb = (const float*)d_in[2];   // [64]
    float* out = (float*)d_out;                // [256, 64]

    dim3 grid(4, KB);   // x-major: the 4 M-tiles sharing a W slice are co-resident (L2 reuse)
    wl_gemm<<<grid, NTHREADS>>>(x, W);
    wl_reduce1<<<512, 256>>>();
    wl_reduce2<<<64, 256>>>(bb, out);
}